// round 2
// baseline (speedup 1.0000x reference)
#include <cuda_runtime.h>
#include <math.h>

#define BS   8
#define NT   128
#define CH   1024
#define KH   4
#define HID  512
#define GD   2048            // 4*HID, gate dim (i,f,g,o)
#define NGRP 8               // 2 dirs * 4 heads
#define MM   (NT*BS)         // 1024 "m" columns = t*8+b

// ---- device scratch (static allocation per harness rules) ----
__device__ float g_Xp[KH * CH * MM];          // [k][c][m]    16.8 MB
__device__ float g_gates[(size_t)NGRP * GD * MM]; // [grp][g][m]  67 MB (includes bias)
__device__ float g_h[2 * NGRP * BS * HID];    // ping-pong h state
__device__ float g_c[NGRP * BS * HID];        // c state

// ---------------------------------------------------------------------------
__global__ void init_state() {
    int i = blockIdx.x * blockDim.x + threadIdx.x;
    if (i < 2 * NGRP * BS * HID) g_h[i] = 0.f;
    if (i < NGRP * BS * HID)     g_c[i] = 0.f;
}

// ---------------------------------------------------------------------------
// Pack inputs [b][t][c][k] -> Xp[k][c][m], m = t*8+b. Coalesced float4 reads.
__global__ void pack_inputs(const float* __restrict__ in) {
    int idx = blockIdx.x * blockDim.x + threadIdx.x;   // over (b,t,c)
    if (idx >= BS * NT * CH) return;
    int c  = idx % CH;
    int bt = idx / CH;
    int t  = bt % NT;
    int b  = bt / NT;
    float4 v = ((const float4*)in)[idx];               // 4 heads contiguous
    int m = t * BS + b;
    g_Xp[0 * CH * MM + c * MM + m] = v.x;
    g_Xp[1 * CH * MM + c * MM + m] = v.y;
    g_Xp[2 * CH * MM + c * MM + m] = v.z;
    g_Xp[3 * CH * MM + c * MM + m] = v.w;
}

// ---------------------------------------------------------------------------
// Input projection: gates[grp][g][m] = sum_c Wih[grp][g][c] * Xp[k][c][m] + bias[g]
// Tiled fp32 GEMM: BM=128 (g) x BN=64 (m) x BK=16, 256 threads, 8x4 per thread.
#define BMg 128
#define BNg 64
#define BKg 16

__global__ void __launch_bounds__(256) input_gemm(
    const float* __restrict__ Wih_f, const float* __restrict__ Wih_b,
    const float* __restrict__ bih_f, const float* __restrict__ bhh_f,
    const float* __restrict__ bih_b, const float* __restrict__ bhh_b)
{
    __shared__ float As[BKg][132];   // [c][g], padded
    __shared__ float Bs[BKg][68];    // [c][m], padded

    int dirk = blockIdx.z;
    int dir  = dirk >> 2;
    int k    = dirk & 3;
    const float* A  = (dir ? Wih_b : Wih_f) + (size_t)k * GD * CH;
    const float* B  = g_Xp + (size_t)k * CH * MM;
    const float* bi = (dir ? bih_b : bih_f) + k * GD;
    const float* bh = (dir ? bhh_b : bhh_f) + k * GD;
    float* C = g_gates + (size_t)dirk * GD * MM;

    int g0 = blockIdx.y * BMg;
    int m0 = blockIdx.x * BNg;
    int tid = threadIdx.x;
    int ty = tid >> 4;       // 0..15 -> 8 g-rows each
    int tx = tid & 15;       // 0..15 -> 4 m-cols each

    float acc[8][4];
#pragma unroll
    for (int i = 0; i < 8; i++)
#pragma unroll
        for (int j = 0; j < 4; j++) acc[i][j] = 0.f;

    for (int c0 = 0; c0 < CH; c0 += BKg) {
#pragma unroll
        for (int e = 0; e < 8; e++) {               // A tile: 128g x 16c
            int lin = e * 256 + tid;
            int cc = lin & 15, gg = lin >> 4;
            As[cc][gg] = A[(size_t)(g0 + gg) * CH + c0 + cc];
        }
#pragma unroll
        for (int e = 0; e < 4; e++) {               // B tile: 16c x 64m
            int lin = e * 256 + tid;
            int mm = lin & 63, cc = lin >> 6;
            Bs[cc][mm] = B[(size_t)(c0 + cc) * MM + m0 + mm];
        }
        __syncthreads();
#pragma unroll
        for (int kk = 0; kk < BKg; kk++) {
            float4 b4 = *(const float4*)&Bs[kk][tx * 4];
            float4 a0 = *(const float4*)&As[kk][ty * 8];
            float4 a1 = *(const float4*)&As[kk][ty * 8 + 4];
            float av[8] = {a0.x, a0.y, a0.z, a0.w, a1.x, a1.y, a1.z, a1.w};
            float bv[4] = {b4.x, b4.y, b4.z, b4.w};
#pragma unroll
            for (int i = 0; i < 8; i++)
#pragma unroll
                for (int j = 0; j < 4; j++) acc[i][j] += av[i] * bv[j];
        }
        __syncthreads();
    }

#pragma unroll
    for (int i = 0; i < 8; i++) {
        int gg = g0 + ty * 8 + i;
        float bias = bi[gg] + bh[gg];
        float4 r;
        r.x = acc[i][0] + bias; r.y = acc[i][1] + bias;
        r.z = acc[i][2] + bias; r.w = acc[i][3] + bias;
        *(float4*)&C[(size_t)gg * MM + m0 + tx * 4] = r;
    }
}

// ---------------------------------------------------------------------------
// One LSTM timestep for all 8 (dir,head) groups, all 8 batches.
// grid = (16 h-slices, 8 groups), 256 threads.
// Thread (r=tid%128, half=tid/128): gate row (gate=r/32, j=slice*32 + r%32),
// batches half*4..half*4+3. Weight float4 feeds 16 FMAs (4 batches).
__global__ void __launch_bounds__(256) lstm_step(
    const float* __restrict__ Whh_f, const float* __restrict__ Whh_b,
    float* __restrict__ out, int t)
{
    __shared__ float hsm[BS * HID];        // h_prev [b][h]
    __shared__ float gsm[4 * 32 * BS];     // [gate][jl][b]

    int grp = blockIdx.y;
    int dir = grp >> 2;
    int k   = grp & 3;
    int tt  = dir ? (NT - 1 - t) : t;
    int tid = threadIdx.x;

    // load h_prev (ping-pong buffer t&1) into smem
    const float4* hsrc = (const float4*)(g_h + ((size_t)(t & 1) * NGRP + grp) * BS * HID);
    float4* hsm4 = (float4*)hsm;
#pragma unroll
    for (int e = 0; e < 4; e++) hsm4[e * 256 + tid] = hsrc[e * 256 + tid];
    __syncthreads();

    int r    = tid & 127;
    int half = tid >> 7;
    int gate = r >> 5;
    int jl   = r & 31;
    int j    = blockIdx.x * 32 + jl;
    int row  = gate * HID + j;
    int bbase = half * 4;

    const float* wr = (dir ? Whh_b : Whh_f) + ((size_t)k * GD + row) * HID;
    const float4* wr4 = (const float4*)wr;
    const float4* h0 = hsm4 + (bbase + 0) * (HID / 4);
    const float4* h1 = hsm4 + (bbase + 1) * (HID / 4);
    const float4* h2 = hsm4 + (bbase + 2) * (HID / 4);
    const float4* h3 = hsm4 + (bbase + 3) * (HID / 4);

    float acc0 = 0.f, acc1 = 0.f, acc2 = 0.f, acc3 = 0.f;
#pragma unroll 8
    for (int q = 0; q < HID / 4; q++) {
        float4 w = wr4[q];
        float4 a = h0[q]; acc0 += w.x*a.x + w.y*a.y + w.z*a.z + w.w*a.w;
        float4 b = h1[q]; acc1 += w.x*b.x + w.y*b.y + w.z*b.z + w.w*b.w;
        float4 c = h2[q]; acc2 += w.x*c.x + w.y*c.y + w.z*c.z + w.w*c.w;
        float4 d = h3[q]; acc3 += w.x*d.x + w.y*d.y + w.z*d.z + w.w*d.w;
    }

    // add precomputed input projection (+bias)
    const float* gin = g_gates + ((size_t)grp * GD + row) * MM + tt * BS + bbase;
    gsm[(gate * 32 + jl) * BS + bbase + 0] = acc0 + gin[0];
    gsm[(gate * 32 + jl) * BS + bbase + 1] = acc1 + gin[1];
    gsm[(gate * 32 + jl) * BS + bbase + 2] = acc2 + gin[2];
    gsm[(gate * 32 + jl) * BS + bbase + 3] = acc3 + gin[3];
    __syncthreads();

    // pointwise LSTM cell: thread -> (jl2, b)
    int jl2 = tid >> 3;
    int b   = tid & 7;
    int j2  = blockIdx.x * 32 + jl2;
    float gi = gsm[(0 * 32 + jl2) * BS + b];
    float gf = gsm[(1 * 32 + jl2) * BS + b];
    float gc = gsm[(2 * 32 + jl2) * BS + b];
    float go = gsm[(3 * 32 + jl2) * BS + b];

    int soff = grp * BS * HID + b * HID + j2;
    float cp = g_c[soff];
    float si = 1.f / (1.f + expf(-gi));
    float sf = 1.f / (1.f + expf(-gf));
    float so = 1.f / (1.f + expf(-go));
    float cn = sf * cp + si * tanhf(gc);
    float hn = so * tanhf(cn);
    g_c[soff] = cn;
    g_h[((size_t)((t + 1) & 1) * NGRP + grp) * BS * HID + b * HID + j2] = hn;

    // out[b][tt][dir*512 + j2][k]
    out[(((size_t)b * NT + tt) * (2 * HID) + dir * HID + j2) * KH + k] = hn;
}

// ---------------------------------------------------------------------------
extern "C" void kernel_launch(void* const* d_in, const int* in_sizes, int n_in,
                              void* d_out, int out_size) {
    const float* inputs = (const float*)d_in[0];
    const float* Wih_f  = (const float*)d_in[1];
    const float* Whh_f  = (const float*)d_in[2];
    const float* bih_f  = (const float*)d_in[3];
    const float* bhh_f  = (const float*)d_in[4];
    const float* Wih_b  = (const float*)d_in[5];
    const float* Whh_b  = (const float*)d_in[6];
    const float* bih_b  = (const float*)d_in[7];
    const float* bhh_b  = (const float*)d_in[8];
    float* out = (float*)d_out;

    init_state<<<(2 * NGRP * BS * HID + 255) / 256, 256>>>();
    pack_inputs<<<(BS * NT * CH + 255) / 256, 256>>>(inputs);

    dim3 gg(MM / BNg, GD / BMg, NGRP);   // (16, 16, 8)
    input_gemm<<<gg, 256>>>(Wih_f, Wih_b, bih_f, bhh_f, bih_b, bhh_b);

    dim3 gs(HID / 32, NGRP);             // (16, 8)
    for (int t = 0; t < NT; t++) {
        lstm_step<<<gs, 256>>>(Whh_f, Whh_b, out, t);
    }
}

// round 3
// speedup vs baseline: 3.3055x; 3.3055x over previous
#include <cuda_runtime.h>
#include <cstdint>
#include <math.h>

#define BS   8
#define NT   128
#define CH   1024
#define KH   4
#define HID  512
#define GD   2048
#define NGRP 8
#define MM   1024

// ---- static device scratch ----
__device__ float4 g_Wa[8u*128*128*32];      // Wih frag-packed  (67MB)
__device__ float4 g_Wr[8u*16*4*8*16*32];    // Whh frag-packed  (33.5MB)
__device__ float2 g_Xp[4u*128*128*32];      // inputs frag-packed (16.8MB)
__device__ float2 g_gates[(size_t)NGRP*GD*512]; // [grp][g][m/2] (67MB)
__device__ float  g_h[2*NGRP*BS*HID];
__device__ float  g_c[NGRP*BS*HID];

// ---- helpers ----
__device__ __forceinline__ uint32_t f2tf(float x) {
    uint32_t r; asm("cvt.rna.tf32.f32 %0, %1;" : "=r"(r) : "f"(x)); return r;
}
__device__ __forceinline__ void mma_tf32(float& c0, float& c1, float& c2, float& c3,
                                         uint32_t a0, uint32_t a1, uint32_t a2, uint32_t a3,
                                         uint32_t b0, uint32_t b1) {
    asm volatile("mma.sync.aligned.m16n8k8.row.col.f32.tf32.tf32.f32 "
        "{%0,%1,%2,%3}, {%4,%5,%6,%7}, {%8,%9}, {%0,%1,%2,%3};\n"
        : "+f"(c0), "+f"(c1), "+f"(c2), "+f"(c3)
        : "r"(a0), "r"(a1), "r"(a2), "r"(a3), "r"(b0), "r"(b1));
}
__device__ __forceinline__ float sigm(float x) { return 1.f / (1.f + __expf(-x)); }
__device__ __forceinline__ float tanh_f(float x) { return 2.f / (1.f + __expf(-2.f * x)) - 1.f; }

// ---------------------------------------------------------------------------
__global__ void init_state() {
    int i = blockIdx.x * blockDim.x + threadIdx.x;
    if (i < 2 * NGRP * BS * HID) g_h[i] = 0.f;
    if (i < NGRP * BS * HID)     g_c[i] = 0.f;
}

// ---------------------------------------------------------------------------
// inputs [b][t][c][k] -> B-fragment pack: g_Xp[kh][mblk][s][l] float2
// element (m,c): mblk=m>>3, s=c>>3, l=((m&7)<<2)|(c&3), half=(c>>2)&1
__global__ void pack_inputs(const float* __restrict__ in) {
    int idx = blockIdx.x * blockDim.x + threadIdx.x;   // (b,t,c)
    if (idx >= BS * NT * CH) return;
    int c  = idx % CH;
    int bt = idx / CH;
    int t  = bt % NT;
    int b  = bt / NT;
    float4 v = ((const float4*)in)[idx];
    int m = t * BS + b;
    int mblk = m >> 3, s = c >> 3;
    int l = ((m & 7) << 2) | (c & 3);
    int half = (c >> 2) & 1;
    float* xp = (float*)g_Xp;
    float vv[4] = {v.x, v.y, v.z, v.w};
#pragma unroll
    for (int kk = 0; kk < 4; kk++) {
        size_t fi = ((((size_t)kk * 128 + mblk) * 128 + s) * 32 + l) * 2 + half;
        xp[fi] = __uint_as_float(f2tf(vv[kk]));
    }
}

// ---------------------------------------------------------------------------
// Wih -> A-frag pack: g_Wa[grp][g16][s][l] = float4(a0,a1,a2,a3)
__global__ void prepack_Wih(const float* __restrict__ Wih_f, const float* __restrict__ Wih_b) {
    int t = blockIdx.x * blockDim.x + threadIdx.x;
    if (t >= 8 * 128 * 128 * 32) return;
    int l = t & 31, s = (t >> 5) & 127, g16 = (t >> 12) & 127, grp = t >> 19;
    int dir = grp >> 2, kh = grp & 3;
    const float* W = (dir ? Wih_b : Wih_f) + (size_t)kh * GD * CH;
    int r = g16 * 16 + (l >> 2);
    int c = s * 8 + (l & 3);
    float4 v;
    v.x = __uint_as_float(f2tf(W[(size_t)r * CH + c]));
    v.y = __uint_as_float(f2tf(W[(size_t)(r + 8) * CH + c]));
    v.z = __uint_as_float(f2tf(W[(size_t)r * CH + c + 4]));
    v.w = __uint_as_float(f2tf(W[(size_t)(r + 8) * CH + c + 4]));
    g_Wa[t] = v;
}

// ---------------------------------------------------------------------------
// Whh -> A-frag pack: g_Wr[((grp*16+sl)*4+q)*8+w][s][l]
__global__ void prepack_Whh(const float* __restrict__ Whh_f, const float* __restrict__ Whh_b) {
    int t = blockIdx.x * blockDim.x + threadIdx.x;
    if (t >= 8 * 16 * 4 * 8 * 16 * 32) return;
    int l = t & 31, s = (t >> 5) & 15, w = (t >> 9) & 7, q = (t >> 12) & 3;
    int sl = (t >> 14) & 15, grp = t >> 18;
    int dir = grp >> 2, kh = grp & 3;
    const float* W = (dir ? Whh_b : Whh_f) + (size_t)kh * GD * HID;
    int r0l = w * 16 + (l >> 2);
    int r1l = r0l + 8;
    int gate = w >> 1;
    int grow0 = gate * HID + sl * 32 + (r0l & 31);
    int grow1 = gate * HID + sl * 32 + (r1l & 31);
    int c = q * 128 + s * 8 + (l & 3);
    float4 v;
    v.x = __uint_as_float(f2tf(W[(size_t)grow0 * HID + c]));
    v.y = __uint_as_float(f2tf(W[(size_t)grow1 * HID + c]));
    v.z = __uint_as_float(f2tf(W[(size_t)grow0 * HID + c + 4]));
    v.w = __uint_as_float(f2tf(W[(size_t)grow1 * HID + c + 4]));
    g_Wr[t] = v;
}

// ---------------------------------------------------------------------------
// Input GEMM (tf32 tensor cores), no smem: frags prepacked in fragment order.
// CTA tile 128(g) x 128(m); warps 4(M)x2(N); warp tile 32x64 = 2 m16 x 8 n8.
__global__ void __launch_bounds__(256) input_gemm(
    const float* __restrict__ bih_f, const float* __restrict__ bhh_f,
    const float* __restrict__ bih_b, const float* __restrict__ bhh_b)
{
    int grp = blockIdx.z, dir = grp >> 2, kh = grp & 3;
    int tid = threadIdx.x, l = tid & 31, warp = tid >> 5;
    int wm = warp & 3, wn = warp >> 2;
    int t0  = blockIdx.y * 8 + wm * 2;        // first m16 tile index
    int mb0 = blockIdx.x * 16 + wn * 8;       // first n8 block index

    const uint4*  A0 = (const uint4*)g_Wa + ((size_t)(grp * 128 + t0) * 128) * 32 + l;
    const uint4*  A1 = A0 + 128 * 32;
    const float2* Bp = g_Xp + ((size_t)(kh * 128 + mb0) * 128) * 32 + l;

    float c[2][8][4];
#pragma unroll
    for (int i = 0; i < 2; i++)
#pragma unroll
        for (int j = 0; j < 8; j++)
#pragma unroll
            for (int e = 0; e < 4; e++) c[i][j][e] = 0.f;

#pragma unroll 2
    for (int s = 0; s < 128; s++) {
        uint4 a0 = A0[(size_t)s * 32];
        uint4 a1 = A1[(size_t)s * 32];
        uint32_t bb0[8], bb1[8];
#pragma unroll
        for (int j = 0; j < 8; j++) {
            float2 bv = Bp[(size_t)j * 128 * 32 + (size_t)s * 32];
            bb0[j] = __float_as_uint(bv.x);
            bb1[j] = __float_as_uint(bv.y);
        }
#pragma unroll
        for (int j = 0; j < 8; j++) {
            mma_tf32(c[0][j][0], c[0][j][1], c[0][j][2], c[0][j][3],
                     a0.x, a0.y, a0.z, a0.w, bb0[j], bb1[j]);
            mma_tf32(c[1][j][0], c[1][j][1], c[1][j][2], c[1][j][3],
                     a1.x, a1.y, a1.z, a1.w, bb0[j], bb1[j]);
        }
    }

    const float* bi = (dir ? bih_b : bih_f) + kh * GD;
    const float* bh = (dir ? bhh_b : bhh_f) + kh * GD;
    int r0 = t0 * 16 + (l >> 2);
#pragma unroll
    for (int i = 0; i < 2; i++) {
        int ra = r0 + i * 16, rb = ra + 8;
        float ba = bi[ra] + bh[ra];
        float bbv = bi[rb] + bh[rb];
#pragma unroll
        for (int j = 0; j < 8; j++) {
            int mhalf = (mb0 + j) * 4 + (l & 3);   // m/2
            g_gates[((size_t)grp * GD + ra) * 512 + mhalf] =
                make_float2(c[i][j][0] + ba, c[i][j][1] + ba);
            g_gates[((size_t)grp * GD + rb) * 512 + mhalf] =
                make_float2(c[i][j][2] + bbv, c[i][j][3] + bbv);
        }
    }
}

// ---------------------------------------------------------------------------
// LSTM step: tensor-core matvec, cp.async double-buffered weight streaming.
// CTA = (sl: 32-j slice, grp). 256 thr = 8 warps; warp w -> 16 rows (gate=w>>1).
#define HPAD 516
__global__ void __launch_bounds__(256) lstm_step_tc(float* __restrict__ out, int t)
{
    extern __shared__ float smem[];
    float4* sW  = (float4*)smem;              // 2 x 4096 float4 (128KB)
    float*  hsm = smem + 32768;               // 8 x 516
    float*  gsm = smem + 32768 + 8 * HPAD;    // 32 x 8 x 4

    int sl = blockIdx.x, grp = blockIdx.y;
    int dir = grp >> 2, kh = grp & 3;
    int tt = dir ? (NT - 1 - t) : t;
    int tid = threadIdx.x, l = tid & 31, w = tid >> 5;

    // load + tf32-round h_prev
    const float* hsrc = g_h + (size_t)((t & 1) * NGRP + grp) * BS * HID;
#pragma unroll
    for (int e = 0; e < 16; e++) {
        int idx = e * 256 + tid;
        hsm[(idx >> 9) * HPAD + (idx & 511)] = __uint_as_float(f2tf(hsrc[idx]));
    }

    const float4* wbase = g_Wr + (size_t)(grp * 16 + sl) * 4 * 4096;

    // prefetch chunk 0
    {
        uint32_t sb = (uint32_t)__cvta_generic_to_shared(sW);
        const float4* g = wbase;
#pragma unroll
        for (int e = 0; e < 16; e++) {
            int idx = e * 256 + tid;
            asm volatile("cp.async.cg.shared.global [%0], [%1], 16;\n"
                         :: "r"(sb + idx * 16), "l"(g + idx));
        }
        asm volatile("cp.async.commit_group;\n");
    }

    float c0 = 0.f, c1 = 0.f, c2 = 0.f, c3 = 0.f;

#pragma unroll
    for (int q = 0; q < 4; q++) {
        if (q < 3) {
            uint32_t sb = (uint32_t)__cvta_generic_to_shared(sW + ((q + 1) & 1) * 4096);
            const float4* g = wbase + (size_t)(q + 1) * 4096;
#pragma unroll
            for (int e = 0; e < 16; e++) {
                int idx = e * 256 + tid;
                asm volatile("cp.async.cg.shared.global [%0], [%1], 16;\n"
                             :: "r"(sb + idx * 16), "l"(g + idx));
            }
            asm volatile("cp.async.commit_group;\n");
            asm volatile("cp.async.wait_group 1;\n");
        } else {
            asm volatile("cp.async.wait_group 0;\n");
        }
        __syncthreads();

        const float4* wc = sW + (q & 1) * 4096 + (w * 16) * 32 + l;
        const float*  hb = hsm + (l >> 2) * HPAD + q * 128 + (l & 3);
#pragma unroll
        for (int s = 0; s < 16; s++) {
            uint4 a = *(const uint4*)(wc + s * 32);
            uint32_t b0 = __float_as_uint(hb[s * 8]);
            uint32_t b1 = __float_as_uint(hb[s * 8 + 4]);
            mma_tf32(c0, c1, c2, c3, a.x, a.y, a.z, a.w, b0, b1);
        }
        __syncthreads();
    }

    // add input-projection gates, exchange to (jl, b, gate) layout
    int r0l = w * 16 + (l >> 2), r1l = r0l + 8;
    int gate = w >> 1;
    int jl0 = r0l & 31, jl1 = r1l & 31;
    int grow0 = gate * HID + sl * 32 + jl0;
    int grow1 = gate * HID + sl * 32 + jl1;
    int bc = (l & 3) * 2;
    float2 gin0 = g_gates[((size_t)grp * GD + grow0) * 512 + tt * 4 + (l & 3)];
    float2 gin1 = g_gates[((size_t)grp * GD + grow1) * 512 + tt * 4 + (l & 3)];
    gsm[(jl0 * 8 + bc) * 4 + gate]     = c0 + gin0.x;
    gsm[(jl0 * 8 + bc + 1) * 4 + gate] = c1 + gin0.y;
    gsm[(jl1 * 8 + bc) * 4 + gate]     = c2 + gin1.x;
    gsm[(jl1 * 8 + bc + 1) * 4 + gate] = c3 + gin1.y;
    __syncthreads();

    // pointwise cell: thread -> (jl, b)
    int jl = tid >> 3, b = tid & 7;
    int gb = (jl * 8 + b) * 4;
    float gi = gsm[gb], gf = gsm[gb + 1], gg = gsm[gb + 2], go = gsm[gb + 3];
    int soff = (grp * BS + b) * HID + sl * 32 + jl;
    float cp = g_c[soff];
    float cn = sigm(gf) * cp + sigm(gi) * tanh_f(gg);
    float hn = sigm(go) * tanh_f(cn);
    g_c[soff] = cn;
    g_h[(size_t)(((t + 1) & 1) * NGRP + grp) * BS * HID + b * HID + sl * 32 + jl] = hn;
    out[(((size_t)b * NT + tt) * (2 * HID) + dir * HID + sl * 32 + jl) * KH + kh] = hn;
}

// ---------------------------------------------------------------------------
extern "C" void kernel_launch(void* const* d_in, const int* in_sizes, int n_in,
                              void* d_out, int out_size) {
    const float* inputs = (const float*)d_in[0];
    const float* Wih_f  = (const float*)d_in[1];
    const float* Whh_f  = (const float*)d_in[2];
    const float* bih_f  = (const float*)d_in[3];
    const float* bhh_f  = (const float*)d_in[4];
    const float* Wih_b  = (const float*)d_in[5];
    const float* Whh_b  = (const float*)d_in[6];
    const float* bih_b  = (const float*)d_in[7];
    const float* bhh_b  = (const float*)d_in[8];
    float* out = (float*)d_out;

    const int SMEM_BYTES = (32768 + 8 * HPAD + 1024) * 4;
    cudaFuncSetAttribute(lstm_step_tc, cudaFuncAttributeMaxDynamicSharedMemorySize, SMEM_BYTES);

    init_state<<<256, 256>>>();
    pack_inputs<<<(BS * NT * CH + 255) / 256, 256>>>(inputs);
    prepack_Wih<<<(8 * 128 * 128 * 32) / 256, 256>>>(Wih_f, Wih_b);
    prepack_Whh<<<(8 * 16 * 4 * 8 * 16 * 32) / 256, 256>>>(Whh_f, Whh_b);

    input_gemm<<<dim3(8, 16, 8), 256>>>(bih_f, bhh_f, bih_b, bhh_b);

    dim3 gs(16, NGRP);
    for (int t = 0; t < NT; t++) {
        lstm_step_tc<<<gs, 256, SMEM_BYTES>>>(out, t);
    }
}

// round 7
// speedup vs baseline: 3.5560x; 1.0758x over previous
#include <cuda_runtime.h>
#include <cstdint>
#include <math.h>

#define BS   8
#define NT   128
#define CH   1024
#define KH   4
#define HID  512
#define GD   2048
#define NGRP 8
#define MM   1024
#define NCTA 148

// ---- static device scratch ----
__device__ float4 g_Wa[8u*128*128*32];        // Wih frag-packed (67MB)
__device__ uint4  g_Wp[1024u*64*32];          // Whh unit-frag-packed (33.5MB)
__device__ float2 g_Xp[4u*128*128*32];        // inputs frag-packed (16.8MB)
__device__ float2 g_gates[(size_t)NGRP*GD*512]; // [grp][grow][m/2] (67MB)
__device__ float2 g_hbuf[129u*NGRP*2048];     // [t][grp][s*32+l] h history (16.9MB)
__device__ unsigned g_bar;

// ---- helpers ----
__device__ __forceinline__ uint32_t f2tf(float x) {
    uint32_t r; asm("cvt.rna.tf32.f32 %0, %1;" : "=r"(r) : "f"(x)); return r;
}
__device__ __forceinline__ void mma_tf32(float& c0, float& c1, float& c2, float& c3,
                                         uint32_t a0, uint32_t a1, uint32_t a2, uint32_t a3,
                                         uint32_t b0, uint32_t b1) {
    asm volatile("mma.sync.aligned.m16n8k8.row.col.f32.tf32.tf32.f32 "
        "{%0,%1,%2,%3}, {%4,%5,%6,%7}, {%8,%9}, {%0,%1,%2,%3};\n"
        : "+f"(c0), "+f"(c1), "+f"(c2), "+f"(c3)
        : "r"(a0), "r"(a1), "r"(a2), "r"(a3), "r"(b0), "r"(b1));
}
__device__ __forceinline__ float sigm(float x) { return 1.f / (1.f + __expf(-x)); }
__device__ __forceinline__ float tanh_f(float x) { return 2.f / (1.f + __expf(-2.f * x)) - 1.f; }

// ---------------------------------------------------------------------------
__global__ void init_state() {
    int i = blockIdx.x * blockDim.x + threadIdx.x;
    if (i == 0) g_bar = 0u;
    if (i < NGRP * 2048) g_hbuf[i] = make_float2(0.f, 0.f);   // h at t=0
}

// ---------------------------------------------------------------------------
// inputs [b][t][c][k] -> B-frag pack g_Xp (tf32-rounded)
__global__ void pack_inputs(const float* __restrict__ in) {
    int idx = blockIdx.x * blockDim.x + threadIdx.x;
    if (idx >= BS * NT * CH) return;
    int c  = idx % CH;
    int bt = idx / CH;
    int t  = bt % NT;
    int b  = bt / NT;
    float4 v = ((const float4*)in)[idx];
    int m = t * BS + b;
    int mblk = m >> 3, s = c >> 3;
    int l = ((m & 7) << 2) | (c & 3);
    int half = (c >> 2) & 1;
    float* xp = (float*)g_Xp;
    float vv[4] = {v.x, v.y, v.z, v.w};
#pragma unroll
    for (int kk = 0; kk < 4; kk++) {
        size_t fi = ((((size_t)kk * 128 + mblk) * 128 + s) * 32 + l) * 2 + half;
        xp[fi] = __uint_as_float(f2tf(vv[kk]));
    }
}

// ---------------------------------------------------------------------------
__global__ void prepack_Wih(const float* __restrict__ Wih_f, const float* __restrict__ Wih_b) {
    int t = blockIdx.x * blockDim.x + threadIdx.x;
    if (t >= 8 * 128 * 128 * 32) return;
    int l = t & 31, s = (t >> 5) & 127, g16 = (t >> 12) & 127, grp = t >> 19;
    int dir = grp >> 2, kh = grp & 3;
    const float* W = (dir ? Wih_b : Wih_f) + (size_t)kh * GD * CH;
    int r = g16 * 16 + (l >> 2);
    int c = s * 8 + (l & 3);
    float4 v;
    v.x = __uint_as_float(f2tf(W[(size_t)r * CH + c]));
    v.y = __uint_as_float(f2tf(W[(size_t)(r + 8) * CH + c]));
    v.z = __uint_as_float(f2tf(W[(size_t)r * CH + c + 4]));
    v.w = __uint_as_float(f2tf(W[(size_t)(r + 8) * CH + c + 4]));
    g_Wa[t] = v;
}

// ---------------------------------------------------------------------------
// Whh -> per-unit A-frag pack. unit = grp*128 + j4 covers rows
// {gate*512 + j4*4 + jj} (16 rows: local row r16 = gate*4+jj), k = 0..511.
// g_Wp[((unit*64 + s)*32 + l)]: a0=row(l>>2), a1=row(l>>2)+8, cols s*8+(l&3), +4.
__global__ void prepack_Wp(const float* __restrict__ Whh_f, const float* __restrict__ Whh_b) {
    int t = blockIdx.x * blockDim.x + threadIdx.x;   // 1024*64*32
    int l = t & 31, s = (t >> 5) & 63, unit = t >> 11;
    int grp = unit >> 7, j4 = unit & 127;
    int dir = grp >> 2, kh = grp & 3;
    const float* W = (dir ? Whh_b : Whh_f) + (size_t)kh * GD * HID;
    int r = l >> 2;                                   // local row 0..7
    int grow0 = (r >> 2) * 512 + j4 * 4 + (r & 3);    // gates 0/1
    int grow1 = grow0 + 1024;                         // gates 2/3
    int c = s * 8 + (l & 3);
    uint4 v;
    v.x = f2tf(W[(size_t)grow0 * HID + c]);
    v.y = f2tf(W[(size_t)grow1 * HID + c]);
    v.z = f2tf(W[(size_t)grow0 * HID + c + 4]);
    v.w = f2tf(W[(size_t)grow1 * HID + c + 4]);
    g_Wp[t] = v;
}

// ---------------------------------------------------------------------------
// Input GEMM (tf32 mma), frags prepacked. CTA 128g x 128m, 8 warps.
__global__ void __launch_bounds__(256) input_gemm(
    const float* __restrict__ bih_f, const float* __restrict__ bhh_f,
    const float* __restrict__ bih_b, const float* __restrict__ bhh_b)
{
    int grp = blockIdx.z, dir = grp >> 2, kh = grp & 3;
    int tid = threadIdx.x, l = tid & 31, warp = tid >> 5;
    int wm = warp & 3, wn = warp >> 2;
    int t0  = blockIdx.y * 8 + wm * 2;
    int mb0 = blockIdx.x * 16 + wn * 8;

    const uint4*  A0 = (const uint4*)g_Wa + ((size_t)(grp * 128 + t0) * 128) * 32 + l;
    const uint4*  A1 = A0 + 128 * 32;
    const float2* Bp = g_Xp + ((size_t)(kh * 128 + mb0) * 128) * 32 + l;

    float c[2][8][4];
#pragma unroll
    for (int i = 0; i < 2; i++)
#pragma unroll
        for (int j = 0; j < 8; j++)
#pragma unroll
            for (int e = 0; e < 4; e++) c[i][j][e] = 0.f;

#pragma unroll 2
    for (int s = 0; s < 128; s++) {
        uint4 a0 = A0[(size_t)s * 32];
        uint4 a1 = A1[(size_t)s * 32];
        uint32_t bb0[8], bb1[8];
#pragma unroll
        for (int j = 0; j < 8; j++) {
            float2 bv = Bp[(size_t)j * 128 * 32 + (size_t)s * 32];
            bb0[j] = __float_as_uint(bv.x);
            bb1[j] = __float_as_uint(bv.y);
        }
#pragma unroll
        for (int j = 0; j < 8; j++) {
            mma_tf32(c[0][j][0], c[0][j][1], c[0][j][2], c[0][j][3],
                     a0.x, a0.y, a0.z, a0.w, bb0[j], bb1[j]);
            mma_tf32(c[1][j][0], c[1][j][1], c[1][j][2], c[1][j][3],
                     a1.x, a1.y, a1.z, a1.w, bb0[j], bb1[j]);
        }
    }

    const float* bi = (dir ? bih_b : bih_f) + kh * GD;
    const float* bh = (dir ? bhh_b : bhh_f) + kh * GD;
    int r0 = t0 * 16 + (l >> 2);
#pragma unroll
    for (int i = 0; i < 2; i++) {
        int ra = r0 + i * 16, rb = ra + 8;
        float ba = bi[ra] + bh[ra];
        float bbv = bi[rb] + bh[rb];
#pragma unroll
        for (int j = 0; j < 8; j++) {
            int mhalf = (mb0 + j) * 4 + (l & 3);
            g_gates[((size_t)grp * GD + ra) * 512 + mhalf] =
                make_float2(c[i][j][0] + ba, c[i][j][1] + ba);
            g_gates[((size_t)grp * GD + rb) * 512 + mhalf] =
                make_float2(c[i][j][2] + bbv, c[i][j][3] + bbv);
        }
    }
}

// ---------------------------------------------------------------------------
// Persistent recurrent kernel: 148 CTAs (1/SM), Whh resident in SMEM.
// 136 CTAs own 7 units (224KB), 12 CTAs own 6. Warp w handles unit ustart+w.
// Per step: mma over 64 ksteps (A from smem, B=h via LDG from fresh per-step
// buffer), add precomputed input gates, shfl-exchange gates, cell update with
// register-resident c-state, write h(t+1) + output, global barrier.
__global__ void __launch_bounds__(256) lstm_persistent(float* __restrict__ out)
{
    extern __shared__ uint4 sW[];
    int tid = threadIdx.x, l = tid & 31, w = tid >> 5;
    int cta = blockIdx.x;
    int nu     = (cta < 136) ? 7 : 6;
    int ustart = (cta < 136) ? cta * 7 : 952 + (cta - 136) * 6;

    // load this CTA's weight units into smem
    {
        uint32_t sb = (uint32_t)__cvta_generic_to_shared(sW);
        const uint4* src = g_Wp + (size_t)ustart * 2048;
        int total = nu * 2048;
        for (int i = tid; i < total; i += 256) {
            asm volatile("cp.async.cg.shared.global [%0], [%1], 16;\n"
                         :: "r"(sb + i * 16), "l"(src + i));
        }
        asm volatile("cp.async.commit_group;\n");
        asm volatile("cp.async.wait_group 0;\n");
    }
    __syncthreads();

    bool active = (w < nu);
    int unit = ustart + (active ? w : 0);
    int grp = unit >> 7, j4 = unit & 127;
    int dir = grp >> 2, kh = grp & 3;

    const uint4* wA = sW + w * 2048 + l;
    int r = l >> 2;
    int ga = (r >> 2) * 512 + j4 * 4 + (r & 3);
    const float2* ginA = g_gates + ((size_t)grp * GD + ga) * 512 + (l & 3);
    const float2* ginB = ginA + (size_t)1024 * 512;

    // output/state indices (lanes < 16)
    int jj = r & 3;               // for lanes<16, r in 0..3 -> jj=r
    int b0 = (l & 3) * 2;
    int j  = j4 * 4 + jj;
    int s_ = j4 >> 1, half = j4 & 1;

    float cs0 = 0.f, cs1 = 0.f;

    for (int t = 0; t < NT; t++) {
        int tt = dir ? (NT - 1 - t) : t;
        float c0 = 0.f, c1 = 0.f, c2 = 0.f, c3 = 0.f;

        if (active) {
            const float2* hrd = g_hbuf + ((size_t)t * NGRP + grp) * 2048 + l;
#pragma unroll 16
            for (int s = 0; s < 64; s++) {
                uint4 a = wA[s * 32];
                float2 hv = __ldg(hrd + s * 32);
                mma_tf32(c0, c1, c2, c3, a.x, a.y, a.z, a.w,
                         __float_as_uint(hv.x), __float_as_uint(hv.y));
            }
            float2 ia = __ldg(ginA + tt * 4);
            float2 ib = __ldg(ginB + tt * 4);
            c0 += ia.x; c1 += ia.y; c2 += ib.x; c3 += ib.y;

            // exchange: lanes<16 hold (i,g), lanes>=16 hold (f,o) for same cells
            float r0 = __shfl_xor_sync(0xffffffffu, c0, 16);
            float r1 = __shfl_xor_sync(0xffffffffu, c1, 16);
            float r2 = __shfl_xor_sync(0xffffffffu, c2, 16);
            float r3 = __shfl_xor_sync(0xffffffffu, c3, 16);

            if (l < 16) {
                float i0 = sigm(c0), f0 = sigm(r0), g0 = tanh_f(c2), o0 = sigm(r2);
                cs0 = f0 * cs0 + i0 * g0;
                float hn0 = o0 * tanh_f(cs0);
                float i1 = sigm(c1), f1 = sigm(r1), g1 = tanh_f(c3), o1 = sigm(r3);
                cs1 = f1 * cs1 + i1 * g1;
                float hn1 = o1 * tanh_f(cs1);

                float* hw = (float*)(g_hbuf + ((size_t)(t + 1) * NGRP + grp) * 2048 + s_ * 32);
                hw[((b0 << 2) | jj) * 2 + half]       = __uint_as_float(f2tf(hn0));
                hw[(((b0 + 1) << 2) | jj) * 2 + half] = __uint_as_float(f2tf(hn1));

                out[(((size_t)b0 * NT + tt) * (2 * HID) + dir * HID + j) * KH + kh] = hn0;
                out[(((size_t)(b0 + 1) * NT + tt) * (2 * HID) + dir * HID + j) * KH + kh] = hn1;
            }
        }

        if (t < NT - 1) {
            __threadfence();
            __syncthreads();
            if (tid == 0) {
                atomicAdd(&g_bar, 1u);
                unsigned target = (unsigned)NCTA * (t + 1);
                unsigned v;
                do {
                    asm volatile("ld.global.acquire.gpu.b32 %0, [%1];"
                                 : "=r"(v) : "l"(&g_bar));
                } while (v < target);
            }
            __syncthreads();
        }
    }
}

// ---------------------------------------------------------------------------
extern "C" void kernel_launch(void* const* d_in, const int* in_sizes, int n_in,
                              void* d_out, int out_size) {
    const float* inputs = (const float*)d_in[0];
    const float* Wih_f  = (const float*)d_in[1];
    const float* Whh_f  = (const float*)d_in[2];
    const float* bih_f  = (const float*)d_in[3];
    const float* bhh_f  = (const float*)d_in[4];
    const float* Wih_b  = (const float*)d_in[5];
    const float* Whh_b  = (const float*)d_in[6];
    const float* bih_b  = (const float*)d_in[7];
    const float* bhh_b  = (const float*)d_in[8];
    float* out = (float*)d_out;

    const int SMEM_BYTES = 7 * 2048 * 16;   // 229376
    cudaFuncSetAttribute(lstm_persistent, cudaFuncAttributeMaxDynamicSharedMemorySize, SMEM_BYTES);

    init_state<<<64, 256>>>();
    pack_inputs<<<(BS * NT * CH + 255) / 256, 256>>>(inputs);
    prepack_Wih<<<(8 * 128 * 128 * 32) / 256, 256>>>(Wih_f, Wih_b);
    prepack_Wp<<<(1024 * 64 * 32) / 256, 256>>>(Whh_f, Whh_b);

    input_gemm<<<dim3(8, 16, 8), 256>>>(bih_f, bhh_f, bih_b, bhh_b);

    lstm_persistent<<<NCTA, 256, SMEM_BYTES>>>(out);
}